// round 4
// baseline (speedup 1.0000x reference)
#include <cuda_runtime.h>
#include <cstdint>

// Problem constants
#define BB 32
#define II 4096
#define VV 512
#define DD 8

// Tiling
#define VT 256          // v per block
#define IC 32           // i per block (split-K chunk)
#define IG 2            // i per pipeline stage
#define NS (IC/IG)      // 16 stages
#define NCHUNK (II/IC)  // 128
#define NRED 8          // second-stage reduction groups
#define NTHREADS 256

__device__ float g_part[NCHUNK][BB * VV];   // split-K partials (8 MB)
__device__ float g_red[NRED][BB * VV];      // second-stage partials (512 KB)

__device__ __forceinline__ void ffma2(unsigned long long& d,
                                      unsigned long long a,
                                      unsigned long long b) {
    asm("fma.rn.f32x2 %0, %1, %2, %0;" : "+l"(d) : "l"(a), "l"(b));
}

__device__ __forceinline__ void cp_async16(float4* smem_dst, const float4* gmem_src) {
    unsigned s = (unsigned)__cvta_generic_to_shared(smem_dst);
    asm volatile("cp.async.cg.shared.global [%0], [%1], 16;"
                 :: "r"(s), "l"(gmem_src));
}
__device__ __forceinline__ void cp_commit() {
    asm volatile("cp.async.commit_group;" ::: "memory");
}
__device__ __forceinline__ void cp_wait1() {
    asm volatile("cp.async.wait_group 1;" ::: "memory");
}
__device__ __forceinline__ void cp_wait0() {
    asm volatile("cp.async.wait_group 0;" ::: "memory");
}

// b-slot permutation so the 4 bg-addresses within a warp are 64B-contiguous
__device__ __forceinline__ int xperm(int b) { return ((b & 7) << 2) | (b >> 3); }

// s_partial[chunk][b,v] = sum over i in chunk, d of W[i,v,d]*x[b,i,d]
// f32x2 lanes = (even-d partial, odd-d partial), summed in epilogue.
__global__ void __launch_bounds__(NTHREADS, 2)
caps_gemm_kernel(const float4* __restrict__ x4, const float4* __restrict__ w4) {
    __shared__ float4 Wsm[2][IG][2][VT];   // 32 KB (double-buffered)
    __shared__ float4 Xsm[2][IG][2][BB];   // 4 KB

    const int tid    = threadIdx.x;
    const int v0     = blockIdx.x * VT;
    const int i_base = blockIdx.y * IC;
    const int bg     = tid & 3;     // quad lane -> b base = bg*8
    const int vg     = tid >> 2;    // 0..63    -> v = v0 + vg + 64*vi

    // X staging indices (stage-invariant); only tid<128 stage X
    const int xs_ig   = tid >> 6;          // 0..1 (for tid<128)
    const int xs_b    = (tid >> 1) & 31;
    const int xs_h    = tid & 1;
    const int xs_slot = xperm(xs_b);

    unsigned long long acc[8][4];
    #pragma unroll
    for (int bi = 0; bi < 8; ++bi)
        #pragma unroll
        for (int vi = 0; vi < 4; ++vi) acc[bi][vi] = 0ull;

    auto load_stage = [&](int s, int buf) {
        const int ib = i_base + s * IG;
        // W: IG rows * 256 v * 2 halves = 1024 float4, coalesced
        #pragma unroll
        for (int k = 0; k < 4; ++k) {
            int t  = tid + k * NTHREADS;      // 0..1023
            int ig = t >> 9;
            int r  = t & 511;
            int vl = r >> 1;
            int h  = r & 1;
            cp_async16(&Wsm[buf][ig][h][vl],
                       &w4[(size_t)(ib + ig) * 1024 + (size_t)(v0 + vl) * 2 + h]);
        }
        // X: IG rows * 32 b * 2 halves = 128 float4
        if (tid < 128)
            cp_async16(&Xsm[buf][xs_ig][xs_h][xs_slot],
                       &x4[(size_t)xs_b * 8192 + (size_t)(ib + xs_ig) * 2 + xs_h]);
    };

    load_stage(0, 0);
    cp_commit();

    for (int s = 0; s < NS; ++s) {
        const int buf = s & 1;
        if (s + 1 < NS) {
            load_stage(s + 1, buf ^ 1);
            cp_commit();
            cp_wait1();
        } else {
            cp_wait0();
        }
        __syncthreads();

        #pragma unroll
        for (int ig = 0; ig < IG; ++ig) {
            #pragma unroll
            for (int h = 0; h < 2; ++h) {
                // W: 8 distinct contiguous float4 per warp -> 1-phase LDS.128
                ulonglong2 wh[4];
                #pragma unroll
                for (int vi = 0; vi < 4; ++vi)
                    wh[vi] = *(const ulonglong2*)&Wsm[buf][ig][h][vg + 64 * vi];
                #pragma unroll
                for (int half = 0; half < 2; ++half) {
                    // X: 4 distinct contiguous float4 per warp (permuted slots)
                    ulonglong2 xh[4];
                    #pragma unroll
                    for (int bi = 0; bi < 4; ++bi) {
                        int slot = (((half * 4 + bi) & 7) << 2) | bg; // xperm(bg*8+bl)
                        xh[bi] = *(const ulonglong2*)&Xsm[buf][ig][h][slot];
                    }
                    #pragma unroll
                    for (int bi = 0; bi < 4; ++bi)
                        #pragma unroll
                        for (int vi = 0; vi < 4; ++vi) {
                            unsigned long long& a = acc[half * 4 + bi][vi];
                            ffma2(a, xh[bi].x, wh[vi].x);
                            ffma2(a, xh[bi].y, wh[vi].y);
                        }
                }
            }
        }
        __syncthreads();
    }

    // ---- epilogue: lo+hi, store partials ----
    float* outp = &g_part[blockIdx.y][0];
    #pragma unroll
    for (int bi = 0; bi < 8; ++bi)
        #pragma unroll
        for (int vi = 0; vi < 4; ++vi) {
            unsigned long long a = acc[bi][vi];
            float lo = __uint_as_float((unsigned)(a & 0xffffffffull));
            float hi = __uint_as_float((unsigned)(a >> 32));
            outp[(bg * 8 + bi) * VV + v0 + vg + 64 * vi] = lo + hi;
        }
}

// First-stage reduction: 256 blocks, each folds 16 chunks for one b.
__global__ void __launch_bounds__(256)
caps_reduce_kernel() {
    const int b   = blockIdx.x;   // 0..31
    const int s   = blockIdx.y;   // 0..7
    const int tid = threadIdx.x;
    #pragma unroll
    for (int j = 0; j < 2; ++j) {
        const int v = tid + j * 256;
        float acc = 0.f;
        #pragma unroll
        for (int c = 0; c < NCHUNK / NRED; ++c)
            acc += g_part[s * (NCHUNK / NRED) + c][b * VV + v];
        g_red[s][b * VV + v] = acc;
    }
}

// Final: fold 8 partials, squash, write (t, outputs) — identical halves.
__global__ void __launch_bounds__(256)
caps_finish_kernel(float* __restrict__ out, int out_size) {
    const int b   = blockIdx.x;   // 32 blocks
    const int tid = threadIdx.x;  // 256 threads
    __shared__ float red[256];

    float local[2];
    #pragma unroll
    for (int j = 0; j < 2; ++j) {
        const int v = tid + j * 256;
        float acc = 0.f;
        #pragma unroll
        for (int c = 0; c < NRED; ++c) acc += g_red[c][b * VV + v];
        local[j] = acc;
    }

    float sq = local[0] * local[0] + local[1] * local[1];
    red[tid] = sq;
    __syncthreads();
    for (int off = 128; off; off >>= 1) {
        if (tid < off) red[tid] += red[tid + off];
        __syncthreads();
    }
    const float total = red[0];
    const float scale = total / ((1.0f + total) * sqrtf(total));

    #pragma unroll
    for (int j = 0; j < 2; ++j) {
        const int v   = tid + j * 256;
        const float o = local[j] * scale;
        const int idx = b * VV + v;
        if (idx < out_size) out[idx] = o;                       // t
        if (idx + BB * VV < out_size) out[idx + BB * VV] = o;   // outputs
    }
}

extern "C" void kernel_launch(void* const* d_in, const int* in_sizes, int n_in,
                              void* d_out, int out_size) {
    const float4* x4 = (const float4*)d_in[0];  // x: [32, 4096, 8] fp32
    const float4* w4 = (const float4*)d_in[1];  // W: [1, 4096, 512, 8] fp32
    float* out = (float*)d_out;

    dim3 grid1(VV / VT, NCHUNK);  // (2, 128)
    caps_gemm_kernel<<<grid1, NTHREADS>>>(x4, w4);
    caps_reduce_kernel<<<dim3(BB, NRED), 256>>>();
    caps_finish_kernel<<<BB, 256>>>(out, out_size);
}

// round 6
// speedup vs baseline: 1.3827x; 1.3827x over previous
#include <cuda_runtime.h>
#include <cstdint>

// Problem constants
#define BB 32
#define II 4096
#define VV 512
#define VTILE 128          // v per CTA (M)
#define CTA_I 32           // i per CTA  -> K = 256
#define STAGE_I 4          // i per stage -> K = 32
#define NS (CTA_I/STAGE_I) // 8 stages
#define NCHUNK (II/CTA_I)  // 128 k-splits
#define NRED 8
#define NTHREADS 256
#define ASTRIDE 36         // floats per A row (32 data + 4 pad): conflict-free frags
#define BSTRIDE 36

__device__ float g_part[NCHUNK][BB * VV];   // split-K partials (8 MB)
__device__ float g_red[NRED][BB * VV];      // second-stage partials

__device__ __forceinline__ void cp_async16(void* smem_dst, const void* gmem_src) {
    unsigned s = (unsigned)__cvta_generic_to_shared(smem_dst);
    asm volatile("cp.async.cg.shared.global [%0], [%1], 16;"
                 :: "r"(s), "l"(gmem_src));
}
__device__ __forceinline__ void cp_commit() {
    asm volatile("cp.async.commit_group;" ::: "memory");
}
__device__ __forceinline__ void cp_wait1() {
    asm volatile("cp.async.wait_group 1;" ::: "memory");
}
__device__ __forceinline__ void cp_wait0() {
    asm volatile("cp.async.wait_group 0;" ::: "memory");
}

// tf32 split: hi = top 19 bits (valid tf32); lo = masked remainder
__device__ __forceinline__ uint32_t tf32_hi(float f) {
    return __float_as_uint(f) & 0xFFFFE000u;
}
__device__ __forceinline__ uint32_t tf32_lo(float f, uint32_t hi) {
    return __float_as_uint(f - __uint_as_float(hi)) & 0xFFFFE000u;
}

__device__ __forceinline__ void mma_tf32(float* c, const uint32_t* a,
                                         const uint32_t* b) {
    asm volatile(
        "mma.sync.aligned.m16n8k8.row.col.f32.tf32.tf32.f32 "
        "{%0,%1,%2,%3}, {%4,%5,%6,%7}, {%8,%9}, {%0,%1,%2,%3};"
        : "+f"(c[0]), "+f"(c[1]), "+f"(c[2]), "+f"(c[3])
        : "r"(a[0]), "r"(a[1]), "r"(a[2]), "r"(a[3]), "r"(b[0]), "r"(b[1]));
}

// D[v_local, b] = sum_k A[v_local,k] * B[k,b];  A = W chunk, B = x chunk (K=256)
__global__ void __launch_bounds__(NTHREADS, 2)
caps_mma_kernel(const float4* __restrict__ x4, const float4* __restrict__ w4) {
    __shared__ float Asm[2][VTILE * ASTRIDE];  // 2 x 18 KB
    __shared__ float Bsm[2][BB * BSTRIDE];     // 2 x 4.5 KB

    const int tid  = threadIdx.x;
    const int w    = tid >> 5;        // warp 0..7 -> m rows [w*16, w*16+16)
    const int lane = tid & 31;
    const int g    = lane >> 2;       // groupID 0..7
    const int t    = lane & 3;        // threadID-in-group 0..3
    const int v0   = blockIdx.x * VTILE;
    const int i0   = blockIdx.y * CTA_I;

    // A staging indices: 1024 16B-chunks/stage, 4 per thread (i_local = k-iter)
    const int a_half = tid & 1;
    const int a_v    = (tid >> 1) & 127;
    // B staging indices: 256 chunks/stage, 1 per thread
    const int b_half = tid & 1;
    const int b_il   = (tid >> 1) & 3;
    const int b_b    = tid >> 3;

    float c[4][4];
    #pragma unroll
    for (int nt = 0; nt < 4; ++nt)
        #pragma unroll
        for (int j = 0; j < 4; ++j) c[nt][j] = 0.f;

    auto load_stage = [&](int s, int buf) {
        const int ib = i0 + s * STAGE_I;
        #pragma unroll
        for (int k = 0; k < 4; ++k) {  // i_local = k
            cp_async16(&Asm[buf][a_v * ASTRIDE + k * 8 + a_half * 4],
                       &w4[((size_t)(ib + k) * 512 + v0 + a_v) * 2 + a_half]);
        }
        cp_async16(&Bsm[buf][b_b * BSTRIDE + b_il * 8 + b_half * 4],
                   &x4[(size_t)b_b * 8192 + (size_t)(ib + b_il) * 2 + b_half]);
    };

    load_stage(0, 0);
    cp_commit();

    for (int s = 0; s < NS; ++s) {
        const int buf = s & 1;
        if (s + 1 < NS) {
            load_stage(s + 1, buf ^ 1);
            cp_commit();
            cp_wait1();
        } else {
            cp_wait0();
        }
        __syncthreads();

        #pragma unroll
        for (int ks = 0; ks < 4; ++ks) {
            // A fragment (m16 k8): rows w*16+g, +8; cols ks*8+t, +4
            const float* ap = &Asm[buf][(w * 16 + g) * ASTRIDE + ks * 8 + t];
            float af[4] = { ap[0], ap[8 * ASTRIDE], ap[4], ap[8 * ASTRIDE + 4] };
            uint32_t ah[4], al[4];
            #pragma unroll
            for (int j = 0; j < 4; ++j) {
                ah[j] = tf32_hi(af[j]);
                al[j] = tf32_lo(af[j], ah[j]);
            }
            #pragma unroll
            for (int nt = 0; nt < 4; ++nt) {
                // B fragment (k8 n8): col n = nt*8+g (b), rows k = ks*8+t, +4
                const float* bp = &Bsm[buf][(nt * 8 + g) * BSTRIDE + ks * 8 + t];
                float bf0 = bp[0], bf1 = bp[4];
                uint32_t bh[2], bl[2];
                bh[0] = tf32_hi(bf0); bl[0] = tf32_lo(bf0, bh[0]);
                bh[1] = tf32_hi(bf1); bl[1] = tf32_lo(bf1, bh[1]);
                mma_tf32(c[nt], ah, bh);
                mma_tf32(c[nt], ah, bl);
                mma_tf32(c[nt], al, bh);
            }
        }
        __syncthreads();
    }

    // ---- epilogue: scatter accumulators to split-K partials ----
    float* outp = &g_part[blockIdx.y][0];
    const int row = w * 16 + g;
    #pragma unroll
    for (int nt = 0; nt < 4; ++nt) {
        const int bc = nt * 8 + t * 2;
        outp[(size_t)bc * VV + v0 + row]           = c[nt][0];
        outp[(size_t)(bc + 1) * VV + v0 + row]     = c[nt][1];
        outp[(size_t)bc * VV + v0 + row + 8]       = c[nt][2];
        outp[(size_t)(bc + 1) * VV + v0 + row + 8] = c[nt][3];
    }
}

// First-stage reduction: 256 blocks, each folds 16 chunks for one b.
__global__ void __launch_bounds__(256)
caps_reduce_kernel() {
    const int b   = blockIdx.x;   // 0..31
    const int s   = blockIdx.y;   // 0..7
    const int tid = threadIdx.x;
    #pragma unroll
    for (int j = 0; j < 2; ++j) {
        const int v = tid + j * 256;
        float acc = 0.f;
        #pragma unroll
        for (int cc = 0; cc < NCHUNK / NRED; ++cc)
            acc += g_part[s * (NCHUNK / NRED) + cc][b * VV + v];
        g_red[s][b * VV + v] = acc;
    }
}

// Final: fold 8 partials, squash, write (t, outputs) — identical halves.
__global__ void __launch_bounds__(256)
caps_finish_kernel(float* __restrict__ out, int out_size) {
    const int b   = blockIdx.x;
    const int tid = threadIdx.x;
    __shared__ float red[256];

    float local[2];
    #pragma unroll
    for (int j = 0; j < 2; ++j) {
        const int v = tid + j * 256;
        float acc = 0.f;
        #pragma unroll
        for (int cc = 0; cc < NRED; ++cc) acc += g_red[cc][b * VV + v];
        local[j] = acc;
    }

    float sq = local[0] * local[0] + local[1] * local[1];
    red[tid] = sq;
    __syncthreads();
    for (int off = 128; off; off >>= 1) {
        if (tid < off) red[tid] += red[tid + off];
        __syncthreads();
    }
    const float total = red[0];
    const float scale = total / ((1.0f + total) * sqrtf(total));

    #pragma unroll
    for (int j = 0; j < 2; ++j) {
        const int v   = tid + j * 256;
        const float o = local[j] * scale;
        const int idx = b * VV + v;
        if (idx < out_size) out[idx] = o;                       // t
        if (idx + BB * VV < out_size) out[idx + BB * VV] = o;   // outputs
    }
}

extern "C" void kernel_launch(void* const* d_in, const int* in_sizes, int n_in,
                              void* d_out, int out_size) {
    const float4* x4 = (const float4*)d_in[0];  // x: [32, 4096, 8] fp32
    const float4* w4 = (const float4*)d_in[1];  // W: [1, 4096, 512, 8] fp32
    float* out = (float*)d_out;

    dim3 grid1(VV / VTILE, NCHUNK);  // (4, 128) = 512 CTAs
    caps_mma_kernel<<<grid1, NTHREADS>>>(x4, w4);
    caps_reduce_kernel<<<dim3(BB, NRED), 256>>>();
    caps_finish_kernel<<<BB, 256>>>(out, out_size);
}